// round 12
// baseline (speedup 1.0000x reference)
#include <cuda_runtime.h>

// inputs: [B=4,C=8,H=256,W=256] f32 ; se_coef scalar f32 ; out [B,C,4,H,W] f32
// scale k: t=4^k, RAD=4*2^k, pen(j)=c*j^2/(4t). closing = Ev(Eh(Dv(Dh(x)))).
// Pads (+-10000 with penalty, pen<=4c=2) can never win vs interior values
// (|v|<~8), so clipped windows / PADV fallbacks match the reference exactly
// (verified rel_err == 0.0 in prior rounds).
// Pairing: pen(j)=pen(-j) -> acc = mm(acc, fma(pc, j^2, mm(vL, vR))).

static constexpr int Wd = 256, Hd = 256, BCn = 32, Sn = 4;

__device__ float g_t1[(size_t)BCn * Sn * Hd * Wd];
__device__ float g_t2[(size_t)BCn * Sn * Hd * Wd];

// ---------------------------------------------------------------------------
// Dh: horizontal dilation, input -> t1. CTA = 16 rows; warp = 2 rows; lane q
// -> outputs x=8q..8q+7 of both rows. Transposed warp-private smem staging
// (conflict-free reads, interior chunks fold to plain LDG+STS).
// ---------------------------------------------------------------------------
template <int K>
__device__ __forceinline__ void dh_impl(float* sb, const float* __restrict__ ext,
                                        const float* __restrict__ cptr)
{
    constexpr int   RAD   = 4 << K;
    constexpr int   SP    = Wd + 2 * RAD;            // 264..320
    constexpr int   NM    = (SP + 31) / 32;          // staging chunks per row
    constexpr int   PITCH = 41;
    constexpr float INV4T = 1.0f / (float)(1 << (2 * K + 2));
    const float pc = -__ldg(cptr) * INV4T;

    const int row0 = blockIdx.x * 16;   // among BC*H = 8192 rows
    const int lane = threadIdx.x & 31, w = threadIdx.x >> 5;
    const int rA = row0 + 2 * w;                     // same bc for both rows
    const int bc = rA >> 8, hA = rA & 255;

    // ---- stage this warp's two padded rows (transposed) ----
    {
        const float* srcA = ext + ((size_t)bc * Hd + hA) * Wd;
        const float* srcB = srcA + Wd;
        float* sdA = sb + ((2 * w) * 8 + (lane & 7)) * PITCH + (lane >> 3);
        float* sdB = sdA + 8 * PITCH;
#pragma unroll
        for (int m = 0; m < NM; ++m) {
            const int xin = lane + 32 * m - RAD;
            if (32 * m >= RAD && 32 * m + 31 - RAD <= Wd - 1) {  // folds
                sdA[4 * m] = srcA[xin];
                sdB[4 * m] = srcB[xin];
            } else {
                const int xc = xin < 0 ? 0 : (xin > Wd - 1 ? Wd - 1 : xin);
                const bool ok = (unsigned)xin < (unsigned)Wd;
                sdA[4 * m] = ok ? srcA[xc] : -10000.0f;
                sdB[4 * m] = ok ? srcB[xc] : -10000.0f;
            }
        }
    }
    __syncwarp();

    const float* rbA = sb + (2 * w) * 8 * PITCH + lane;
    const float* rbB = rbA + 8 * PITCH;
#define CA(C) ((((C) & 7) * PITCH) + ((C) >> 3))

    float aA[8], aB[8], LA[8], RA_[8], LB[8], RB[8];
#pragma unroll
    for (int rr = 0; rr < 8; ++rr) {
        aA[rr] = rbA[CA(RAD + rr)];  LA[rr] = aA[rr];  RA_[rr] = aA[rr];
        aB[rr] = rbB[CA(RAD + rr)];  LB[rr] = aB[rr];  RB[rr] = aB[rr];
    }
#pragma unroll
    for (int j = 1; j <= RAD; ++j) {
#pragma unroll
        for (int i = 7; i > 0; --i) { LA[i] = LA[i - 1]; LB[i] = LB[i - 1]; }
        LA[0] = rbA[CA(RAD - j)];
        LB[0] = rbB[CA(RAD - j)];
#pragma unroll
        for (int i = 0; i < 7; ++i) { RA_[i] = RA_[i + 1]; RB[i] = RB[i + 1]; }
        RA_[7] = rbA[CA(RAD + 7 + j)];
        RB[7] = rbB[CA(RAD + 7 + j)];
        const float pj = (float)(j * j);
#pragma unroll
        for (int rr = 0; rr < 8; ++rr) {
            aA[rr] = fmaxf(aA[rr], fmaf(pc, pj, fmaxf(LA[rr], RA_[rr])));
            aB[rr] = fmaxf(aB[rr], fmaf(pc, pj, fmaxf(LB[rr], RB[rr])));
        }
    }
#undef CA

    float* dp = g_t1 + (((size_t)bc * Sn + K) * Hd + hA) * Wd + lane * 8;
    reinterpret_cast<float4*>(dp)[0] = make_float4(aA[0], aA[1], aA[2], aA[3]);
    reinterpret_cast<float4*>(dp)[1] = make_float4(aA[4], aA[5], aA[6], aA[7]);
    reinterpret_cast<float4*>(dp + Wd)[0] = make_float4(aB[0], aB[1], aB[2], aB[3]);
    reinterpret_cast<float4*>(dp + Wd)[1] = make_float4(aB[4], aB[5], aB[6], aB[7]);
}

__global__ void __launch_bounds__(256, 4) dh_all(const float* __restrict__ ext,
                                                 const float* __restrict__ cptr)
{
    __shared__ float sb[16 * 8 * 41];         // 21 KB
    switch (blockIdx.y) {                     // K outermost -> homogeneous waves
        case 0:  dh_impl<0>(sb, ext, cptr); break;
        case 1:  dh_impl<1>(sb, ext, cptr); break;
        case 2:  dh_impl<2>(sb, ext, cptr); break;
        default: dh_impl<3>(sb, ext, cptr); break;
    }
}

// ---------------------------------------------------------------------------
// Vertical streaming helper (16 rows/thread-col); loads batched 4 j-steps
// ahead (8 back-to-back LDG, MLP=8) to cover L2 latency. RAD % 4 == 0.
// ---------------------------------------------------------------------------
template <int RAD, bool ISMAX, bool SAFE>
__device__ __forceinline__ void vstream(const float* __restrict__ sp,
                                        const int r0, const float pc,
                                        float acc[16])
{
    constexpr float PADV = ISMAX ? -10000.0f : 10000.0f;
#define VLD(ROW)                                                               \
    (SAFE ? sp[(size_t)(ROW) * Wd]                                             \
          : (((unsigned)(ROW) < (unsigned)Hd) ? sp[(size_t)(ROW) * Wd] : PADV))

    float T[16], B[16];
#pragma unroll
    for (int rr = 0; rr < 16; ++rr) {
        acc[rr] = VLD(r0 + rr);
        T[rr] = acc[rr];
        B[rr] = acc[rr];
    }
#pragma unroll
    for (int jb = 1; jb <= RAD; jb += 4) {
        float nt[4], nb[4];
#pragma unroll
        for (int u = 0; u < 4; ++u) {
            nt[u] = VLD(r0 - (jb + u));
            nb[u] = VLD(r0 + 15 + (jb + u));
        }
#pragma unroll
        for (int u = 0; u < 4; ++u) {
#pragma unroll
            for (int i = 15; i > 0; --i) T[i] = T[i - 1];
            T[0] = nt[u];
#pragma unroll
            for (int i = 0; i < 15; ++i) B[i] = B[i + 1];
            B[15] = nb[u];
            const int j = jb + u;
            const float pj = (float)(j * j);
#pragma unroll
            for (int rr = 0; rr < 16; ++rr) {
                const float m = ISMAX ? fmaxf(T[rr], B[rr]) : fminf(T[rr], B[rr]);
                const float t = fmaf(pc, pj, m);
                acc[rr] = ISMAX ? fmaxf(acc[rr], t) : fminf(acc[rr], t);
            }
        }
    }
#undef VLD
}

// ---------------------------------------------------------------------------
// Fused Dv + Eh: t1 -> vertical dilation -> transposed padded smem tile ->
// horizontal erosion (warp = 2 rows, 8 outputs each) -> t2.
// ---------------------------------------------------------------------------
template <int K>
__device__ __forceinline__ void dveh_impl(float* sb, const float* __restrict__ cptr)
{
    constexpr int   RAD   = 4 << K;
    constexpr int   SPW   = Wd + 2 * RAD;
    constexpr int   PITCH = SPW / 8 + 1;      // 34/37/41/49
    constexpr float INV4T = 1.0f / (float)(1 << (2 * K + 2));
    const float cc  = __ldg(cptr);
    const float pcD = -cc * INV4T;
    const float pcE =  cc * INV4T;

    const int x  = threadIdx.x;
    const int r0 = blockIdx.x * 16;
    const int bc = blockIdx.y;

    // ---- vertical dilation ----
    const float* sp = g_t1 + ((size_t)(bc * Sn + K) * Hd) * Wd + x;
    float acc[16];
    if (r0 >= RAD && r0 + 15 + RAD < Hd)
        vstream<RAD, true, true >(sp, r0, pcD, acc);
    else
        vstream<RAD, true, false>(sp, r0, pcD, acc);

    // ---- stash transposed, pad cols with +10000 ----
    {
        const int X = x + RAD;
        const int ca = (X & 7) * PITCH + (X >> 3);
#pragma unroll
        for (int rr = 0; rr < 16; ++rr) sb[rr * 8 * PITCH + ca] = acc[rr];
        for (int i = threadIdx.x; i < 2 * RAD * 16; i += 256) {
            const int col = i & (2 * RAD - 1), r = i / (2 * RAD);
            const int Xp = (col < RAD) ? col : (col + Wd);
            sb[(r * 8 + (Xp & 7)) * PITCH + (Xp >> 3)] = 10000.0f;
        }
    }
    __syncthreads();

    // ---- horizontal erosion: warp w -> rows 2w, 2w+1 ----
    const int w = threadIdx.x >> 5, q = threadIdx.x & 31;
    const float* rbA = sb + (2 * w) * 8 * PITCH + q;
    const float* rbB = rbA + 8 * PITCH;
#define CA(C) ((((C) & 7) * PITCH) + ((C) >> 3))

    float eA[8], eB[8], LA[8], RA_[8], LB[8], RB[8];
#pragma unroll
    for (int rr = 0; rr < 8; ++rr) {
        eA[rr] = rbA[CA(RAD + rr)];  LA[rr] = eA[rr];  RA_[rr] = eA[rr];
        eB[rr] = rbB[CA(RAD + rr)];  LB[rr] = eB[rr];  RB[rr] = eB[rr];
    }
#pragma unroll
    for (int j = 1; j <= RAD; ++j) {
#pragma unroll
        for (int i = 7; i > 0; --i) { LA[i] = LA[i - 1]; LB[i] = LB[i - 1]; }
        LA[0] = rbA[CA(RAD - j)];
        LB[0] = rbB[CA(RAD - j)];
#pragma unroll
        for (int i = 0; i < 7; ++i) { RA_[i] = RA_[i + 1]; RB[i] = RB[i + 1]; }
        RA_[7] = rbA[CA(RAD + 7 + j)];
        RB[7] = rbB[CA(RAD + 7 + j)];
        const float pj = (float)(j * j);
#pragma unroll
        for (int rr = 0; rr < 8; ++rr) {
            eA[rr] = fminf(eA[rr], fmaf(pcE, pj, fminf(LA[rr], RA_[rr])));
            eB[rr] = fminf(eB[rr], fmaf(pcE, pj, fminf(LB[rr], RB[rr])));
        }
    }
#undef CA

    float* dp = g_t2 + (((size_t)bc * Sn + K) * Hd + r0 + 2 * w) * Wd + q * 8;
    reinterpret_cast<float4*>(dp)[0] = make_float4(eA[0], eA[1], eA[2], eA[3]);
    reinterpret_cast<float4*>(dp)[1] = make_float4(eA[4], eA[5], eA[6], eA[7]);
    reinterpret_cast<float4*>(dp + Wd)[0] = make_float4(eB[0], eB[1], eB[2], eB[3]);
    reinterpret_cast<float4*>(dp + Wd)[1] = make_float4(eB[4], eB[5], eB[6], eB[7]);
}

__global__ void __launch_bounds__(256, 3) dveh_all(const float* __restrict__ cptr)
{
    __shared__ float sb[16 * 8 * 49];         // K=3 worst case (24.5 KB)
    switch (blockIdx.z) {
        case 0:  dveh_impl<0>(sb, cptr); break;
        case 1:  dveh_impl<1>(sb, cptr); break;
        case 2:  dveh_impl<2>(sb, cptr); break;
        default: dveh_impl<3>(sb, cptr); break;
    }
}

// ---------------------------------------------------------------------------
// Ev: vertical erosion, t2 -> out. 16 rows/thread-col, batched loads.
// ---------------------------------------------------------------------------
template <int K>
__device__ __forceinline__ void ev_impl(float* __restrict__ out,
                                        const float* __restrict__ cptr)
{
    constexpr int   RAD   = 4 << K;
    constexpr float INV4T = 1.0f / (float)(1 << (2 * K + 2));
    const float pc = __ldg(cptr) * INV4T;

    const int x  = threadIdx.x;
    const int r0 = blockIdx.x * 16;
    const int bc = blockIdx.y;

    const float* sp = g_t2 + ((size_t)(bc * Sn + K) * Hd) * Wd + x;
    float acc[16];
    if (r0 >= RAD && r0 + 15 + RAD < Hd)
        vstream<RAD, false, true >(sp, r0, pc, acc);
    else
        vstream<RAD, false, false>(sp, r0, pc, acc);

    float* dp = out + (((size_t)bc * Sn + K) * Hd + r0) * Wd + x;
#pragma unroll
    for (int rr = 0; rr < 16; ++rr) dp[(size_t)rr * Wd] = acc[rr];
}

__global__ void __launch_bounds__(256, 4) ev_all(float* __restrict__ out,
                                                 const float* __restrict__ cptr)
{
    switch (blockIdx.z) {
        case 0:  ev_impl<0>(out, cptr); break;
        case 1:  ev_impl<1>(out, cptr); break;
        case 2:  ev_impl<2>(out, cptr); break;
        default: ev_impl<3>(out, cptr); break;
    }
}

// ---------------------------------------------------------------------------
// 3 launches: Dh ; Dv+Eh fused ; Ev.  Graph-capturable, no allocations.
// ---------------------------------------------------------------------------
extern "C" void kernel_launch(void* const* d_in, const int* in_sizes, int n_in,
                              void* d_out, int out_size)
{
    const float* in = (const float*)d_in[0];
    const float* cp = (const float*)d_in[1];
    float* out = (float*)d_out;

    dh_all  <<<dim3(BCn * Hd / 16, Sn), 256>>>(in, cp);   // in -> t1
    dveh_all<<<dim3(Hd / 16, BCn, Sn), 256>>>(cp);        // t1 -> t2
    ev_all  <<<dim3(Hd / 16, BCn, Sn), 256>>>(out, cp);   // t2 -> out
}

// round 13
// speedup vs baseline: 1.0983x; 1.0983x over previous
#include <cuda_runtime.h>

// inputs: [B=4,C=8,H=256,W=256] f32 ; se_coef scalar f32 ; out [B,C,4,H,W] f32
// scale k: t=4^k, RAD=4*2^k, pen(j)=c*j^2/(4t). closing = Ev(Eh(Dv(Dh(x)))).
// Pads (+-10000 with penalty, pen<=4c=2) can never win vs interior values
// (|v|<~8), so clipped windows / PADV fallbacks match the reference exactly
// (verified rel_err == 0.0 in prior rounds).
// Pairing: pen(j)=pen(-j) -> acc = mm(acc, fma(pc, j^2, mm(vL, vR))).

static constexpr int Wd = 256, Hd = 256, BCn = 32, Sn = 4;

__device__ float g_t1[(size_t)BCn * Sn * Hd * Wd];
__device__ float g_t2[(size_t)BCn * Sn * Hd * Wd];

// ---------------------------------------------------------------------------
// Dh: horizontal dilation, input -> t1. CTA = 8 rows; warp = row; lane q ->
// outputs x=8q..8q+7. Transposed warp-private smem staging (conflict-free
// reads; interior chunks fold to plain LDG+STS under full unroll).
// ---------------------------------------------------------------------------
template <int K>
__device__ __forceinline__ void dh_impl(float* sb, const float* __restrict__ ext,
                                        const float* __restrict__ cptr)
{
    constexpr int   RAD   = 4 << K;
    constexpr int   SP    = Wd + 2 * RAD;            // 264..320
    constexpr int   NM    = (SP + 31) / 32;          // staging chunks per row
    constexpr int   PITCH = 41;
    constexpr float INV4T = 1.0f / (float)(1 << (2 * K + 2));
    const float pc = -__ldg(cptr) * INV4T;

    const int row0 = blockIdx.x * 8;   // among BC*H = 8192 rows
    const int lane = threadIdx.x & 31, wr = threadIdx.x >> 5;
    const int gr = row0 + wr, bc = gr >> 8, h = gr & 255;

    // ---- stage this warp's padded row (transposed) ----
    {
        const float* src = ext + ((size_t)bc * Hd + h) * Wd;
        float* sdst = sb + (wr * 8 + (lane & 7)) * PITCH + (lane >> 3);
#pragma unroll
        for (int m = 0; m < NM; ++m) {
            const int xin = lane + 32 * m - RAD;
            if (32 * m >= RAD && 32 * m + 31 - RAD <= Wd - 1) {  // folds
                sdst[4 * m] = src[xin];
            } else {
                const int xc = xin < 0 ? 0 : (xin > Wd - 1 ? Wd - 1 : xin);
                const float lv = src[xc];
                sdst[4 * m] = ((unsigned)xin < (unsigned)Wd) ? lv : -10000.0f;
            }
        }
    }
    __syncwarp();

    const float* rowb = sb + wr * 8 * PITCH + lane;
#define HLD(C) rowb[(((C) & 7) * PITCH) + ((C) >> 3)]

    float acc[8], L[8], R[8];
#pragma unroll
    for (int rr = 0; rr < 8; ++rr) {
        acc[rr] = HLD(RAD + rr);   // j = 0 term (pen = 0)
        L[rr] = acc[rr];
        R[rr] = acc[rr];
    }
#pragma unroll
    for (int j = 1; j <= RAD; ++j) {
#pragma unroll
        for (int i = 7; i > 0; --i) L[i] = L[i - 1];
        L[0] = HLD(RAD - j);
#pragma unroll
        for (int i = 0; i < 7; ++i) R[i] = R[i + 1];
        R[7] = HLD(RAD + 7 + j);
        const float pj = (float)(j * j);
#pragma unroll
        for (int rr = 0; rr < 8; ++rr)
            acc[rr] = fmaxf(acc[rr], fmaf(pc, pj, fmaxf(L[rr], R[rr])));
    }
#undef HLD

    float* dp = g_t1 + (((size_t)bc * Sn + K) * Hd + h) * Wd + lane * 8;
    reinterpret_cast<float4*>(dp)[0] = make_float4(acc[0], acc[1], acc[2], acc[3]);
    reinterpret_cast<float4*>(dp)[1] = make_float4(acc[4], acc[5], acc[6], acc[7]);
}

__global__ void __launch_bounds__(256) dh_all(const float* __restrict__ ext,
                                              const float* __restrict__ cptr)
{
    __shared__ float sb[8 * 41 * 8];
    switch (blockIdx.y) {                     // K outermost -> homogeneous waves
        case 0:  dh_impl<0>(sb, ext, cptr); break;
        case 1:  dh_impl<1>(sb, ext, cptr); break;
        case 2:  dh_impl<2>(sb, ext, cptr); break;
        default: dh_impl<3>(sb, ext, cptr); break;
    }
}

// ---------------------------------------------------------------------------
// Vertical streaming helper (16 rows/thread-col); loads batched 4 j-steps
// ahead (8 back-to-back LDG, MLP=8) to cover L2 latency. RAD % 4 == 0.
// ---------------------------------------------------------------------------
template <int RAD, bool ISMAX, bool SAFE>
__device__ __forceinline__ void vstream(const float* __restrict__ sp,
                                        const int r0, const float pc,
                                        float acc[16])
{
    constexpr float PADV = ISMAX ? -10000.0f : 10000.0f;
#define VLD(ROW)                                                               \
    (SAFE ? sp[(size_t)(ROW) * Wd]                                             \
          : (((unsigned)(ROW) < (unsigned)Hd) ? sp[(size_t)(ROW) * Wd] : PADV))

    float T[16], B[16];
#pragma unroll
    for (int rr = 0; rr < 16; ++rr) {
        acc[rr] = VLD(r0 + rr);
        T[rr] = acc[rr];
        B[rr] = acc[rr];
    }
#pragma unroll
    for (int jb = 1; jb <= RAD; jb += 4) {
        float nt[4], nb[4];
#pragma unroll
        for (int u = 0; u < 4; ++u) {
            nt[u] = VLD(r0 - (jb + u));
            nb[u] = VLD(r0 + 15 + (jb + u));
        }
#pragma unroll
        for (int u = 0; u < 4; ++u) {
#pragma unroll
            for (int i = 15; i > 0; --i) T[i] = T[i - 1];
            T[0] = nt[u];
#pragma unroll
            for (int i = 0; i < 15; ++i) B[i] = B[i + 1];
            B[15] = nb[u];
            const int j = jb + u;
            const float pj = (float)(j * j);
#pragma unroll
            for (int rr = 0; rr < 16; ++rr) {
                const float m = ISMAX ? fmaxf(T[rr], B[rr]) : fminf(T[rr], B[rr]);
                const float t = fmaf(pc, pj, m);
                acc[rr] = ISMAX ? fmaxf(acc[rr], t) : fminf(acc[rr], t);
            }
        }
    }
#undef VLD
}

// ---------------------------------------------------------------------------
// Fused Dv + Eh: t1 -> vertical dilation -> transposed padded smem tile ->
// horizontal erosion (warp = 2 rows, 8 outputs each) -> t2.
// ---------------------------------------------------------------------------
template <int K>
__device__ __forceinline__ void dveh_impl(float* sb, const float* __restrict__ cptr)
{
    constexpr int   RAD   = 4 << K;
    constexpr int   SPW   = Wd + 2 * RAD;
    constexpr int   PITCH = SPW / 8 + 1;      // 34/37/41/49
    constexpr float INV4T = 1.0f / (float)(1 << (2 * K + 2));
    const float cc  = __ldg(cptr);
    const float pcD = -cc * INV4T;
    const float pcE =  cc * INV4T;

    const int x  = threadIdx.x;
    const int r0 = blockIdx.x * 16;
    const int bc = blockIdx.y;

    // ---- vertical dilation ----
    const float* sp = g_t1 + ((size_t)(bc * Sn + K) * Hd) * Wd + x;
    float acc[16];
    if (r0 >= RAD && r0 + 15 + RAD < Hd)
        vstream<RAD, true, true >(sp, r0, pcD, acc);
    else
        vstream<RAD, true, false>(sp, r0, pcD, acc);

    // ---- stash transposed, pad cols with +10000 ----
    {
        const int X = x + RAD;
        const int ca = (X & 7) * PITCH + (X >> 3);
#pragma unroll
        for (int rr = 0; rr < 16; ++rr) sb[rr * 8 * PITCH + ca] = acc[rr];
        for (int i = threadIdx.x; i < 2 * RAD * 16; i += 256) {
            const int col = i & (2 * RAD - 1), r = i / (2 * RAD);
            const int Xp = (col < RAD) ? col : (col + Wd);
            sb[(r * 8 + (Xp & 7)) * PITCH + (Xp >> 3)] = 10000.0f;
        }
    }
    __syncthreads();

    // ---- horizontal erosion: warp w -> rows 2w, 2w+1 ----
    const int w = threadIdx.x >> 5, q = threadIdx.x & 31;
    const float* rbA = sb + (2 * w) * 8 * PITCH + q;
    const float* rbB = rbA + 8 * PITCH;
#define CA(C) ((((C) & 7) * PITCH) + ((C) >> 3))

    float eA[8], eB[8], LA[8], RA_[8], LB[8], RB[8];
#pragma unroll
    for (int rr = 0; rr < 8; ++rr) {
        eA[rr] = rbA[CA(RAD + rr)];  LA[rr] = eA[rr];  RA_[rr] = eA[rr];
        eB[rr] = rbB[CA(RAD + rr)];  LB[rr] = eB[rr];  RB[rr] = eB[rr];
    }
#pragma unroll
    for (int j = 1; j <= RAD; ++j) {
#pragma unroll
        for (int i = 7; i > 0; --i) { LA[i] = LA[i - 1]; LB[i] = LB[i - 1]; }
        LA[0] = rbA[CA(RAD - j)];
        LB[0] = rbB[CA(RAD - j)];
#pragma unroll
        for (int i = 0; i < 7; ++i) { RA_[i] = RA_[i + 1]; RB[i] = RB[i + 1]; }
        RA_[7] = rbA[CA(RAD + 7 + j)];
        RB[7] = rbB[CA(RAD + 7 + j)];
        const float pj = (float)(j * j);
#pragma unroll
        for (int rr = 0; rr < 8; ++rr) {
            eA[rr] = fminf(eA[rr], fmaf(pcE, pj, fminf(LA[rr], RA_[rr])));
            eB[rr] = fminf(eB[rr], fmaf(pcE, pj, fminf(LB[rr], RB[rr])));
        }
    }
#undef CA

    float* dp = g_t2 + (((size_t)bc * Sn + K) * Hd + r0 + 2 * w) * Wd + q * 8;
    reinterpret_cast<float4*>(dp)[0] = make_float4(eA[0], eA[1], eA[2], eA[3]);
    reinterpret_cast<float4*>(dp)[1] = make_float4(eA[4], eA[5], eA[6], eA[7]);
    reinterpret_cast<float4*>(dp + Wd)[0] = make_float4(eB[0], eB[1], eB[2], eB[3]);
    reinterpret_cast<float4*>(dp + Wd)[1] = make_float4(eB[4], eB[5], eB[6], eB[7]);
}

__global__ void __launch_bounds__(256, 4) dveh_all(const float* __restrict__ cptr)
{
    __shared__ float sb[16 * 8 * 49];         // K=3 worst case (24.5 KB)
    switch (blockIdx.z) {
        case 0:  dveh_impl<0>(sb, cptr); break;
        case 1:  dveh_impl<1>(sb, cptr); break;
        case 2:  dveh_impl<2>(sb, cptr); break;
        default: dveh_impl<3>(sb, cptr); break;
    }
}

// ---------------------------------------------------------------------------
// Ev: vertical erosion, t2 -> out. 16 rows/thread-col, batched loads.
// ---------------------------------------------------------------------------
template <int K>
__device__ __forceinline__ void ev_impl(float* __restrict__ out,
                                        const float* __restrict__ cptr)
{
    constexpr int   RAD   = 4 << K;
    constexpr float INV4T = 1.0f / (float)(1 << (2 * K + 2));
    const float pc = __ldg(cptr) * INV4T;

    const int x  = threadIdx.x;
    const int r0 = blockIdx.x * 16;
    const int bc = blockIdx.y;

    const float* sp = g_t2 + ((size_t)(bc * Sn + K) * Hd) * Wd + x;
    float acc[16];
    if (r0 >= RAD && r0 + 15 + RAD < Hd)
        vstream<RAD, false, true >(sp, r0, pc, acc);
    else
        vstream<RAD, false, false>(sp, r0, pc, acc);

    float* dp = out + (((size_t)bc * Sn + K) * Hd + r0) * Wd + x;
#pragma unroll
    for (int rr = 0; rr < 16; ++rr) dp[(size_t)rr * Wd] = acc[rr];
}

__global__ void __launch_bounds__(256, 4) ev_all(float* __restrict__ out,
                                                 const float* __restrict__ cptr)
{
    switch (blockIdx.z) {
        case 0:  ev_impl<0>(out, cptr); break;
        case 1:  ev_impl<1>(out, cptr); break;
        case 2:  ev_impl<2>(out, cptr); break;
        default: ev_impl<3>(out, cptr); break;
    }
}

// ---------------------------------------------------------------------------
// 3 launches: Dh ; Dv+Eh fused ; Ev.  Graph-capturable, no allocations.
// ---------------------------------------------------------------------------
extern "C" void kernel_launch(void* const* d_in, const int* in_sizes, int n_in,
                              void* d_out, int out_size)
{
    const float* in = (const float*)d_in[0];
    const float* cp = (const float*)d_in[1];
    float* out = (float*)d_out;

    dh_all  <<<dim3(BCn * Hd / 8, Sn), 256>>>(in, cp);   // in -> t1
    dveh_all<<<dim3(Hd / 16, BCn, Sn), 256>>>(cp);       // t1 -> t2
    ev_all  <<<dim3(Hd / 16, BCn, Sn), 256>>>(out, cp);  // t2 -> out
}

// round 15
// speedup vs baseline: 1.2951x; 1.1792x over previous
#include <cuda_runtime.h>

// inputs: [B=4,C=8,H=256,W=256] f32 ; se_coef scalar f32 ; out [B,C,4,H,W] f32
// scale k: t=4^k, RAD=4*2^k, pen(j)=c*j^2/(4t). closing = Ev(Eh(Dv(Dh(x)))).
// Pads (+-10000 with penalty, pen<=4c=2) can never win vs interior values
// (|v|<~8), so clipped windows / PADV fallbacks match the reference exactly
// (verified rel_err == 0.0 in prior rounds).
// Pairing: pen(j)=pen(-j) -> acc = mm(acc, fma(pc, j^2, mm(vL, vR))).
// K dispatched heavy-first (K=3 first) so wave tails are made of cheap CTAs.

static constexpr int Wd = 256, Hd = 256, BCn = 32, Sn = 4;

__device__ float g_t1[(size_t)BCn * Sn * Hd * Wd];
__device__ float g_t2[(size_t)BCn * Sn * Hd * Wd];

// ---------------------------------------------------------------------------
// Dh: horizontal dilation, input -> t1. CTA = 8 rows; warp = row; lane q ->
// outputs x=8q..8q+7. Transposed warp-private smem staging (conflict-free
// reads; interior chunks fold to plain LDG+STS under full unroll).
// ---------------------------------------------------------------------------
template <int K>
__device__ __forceinline__ void dh_impl(float* sb, const float* __restrict__ ext,
                                        const float* __restrict__ cptr)
{
    constexpr int   RAD   = 4 << K;
    constexpr int   SP    = Wd + 2 * RAD;            // 264..320
    constexpr int   NM    = (SP + 31) / 32;          // staging chunks per row
    constexpr int   PITCH = 41;
    constexpr float INV4T = 1.0f / (float)(1 << (2 * K + 2));
    const float pc = -__ldg(cptr) * INV4T;

    const int row0 = blockIdx.x * 8;   // among BC*H = 8192 rows
    const int lane = threadIdx.x & 31, wr = threadIdx.x >> 5;
    const int gr = row0 + wr, bc = gr >> 8, h = gr & 255;

    // ---- stage this warp's padded row (transposed) ----
    {
        const float* src = ext + ((size_t)bc * Hd + h) * Wd;
        float* sdst = sb + (wr * 8 + (lane & 7)) * PITCH + (lane >> 3);
#pragma unroll
        for (int m = 0; m < NM; ++m) {
            const int xin = lane + 32 * m - RAD;
            if (32 * m >= RAD && 32 * m + 31 - RAD <= Wd - 1) {  // folds
                sdst[4 * m] = src[xin];
            } else {
                const int xc = xin < 0 ? 0 : (xin > Wd - 1 ? Wd - 1 : xin);
                const float lv = src[xc];
                sdst[4 * m] = ((unsigned)xin < (unsigned)Wd) ? lv : -10000.0f;
            }
        }
    }
    __syncwarp();

    const float* rowb = sb + wr * 8 * PITCH + lane;
#define HLD(C) rowb[(((C) & 7) * PITCH) + ((C) >> 3)]

    float acc[8], L[8], R[8];
#pragma unroll
    for (int rr = 0; rr < 8; ++rr) {
        acc[rr] = HLD(RAD + rr);   // j = 0 term (pen = 0)
        L[rr] = acc[rr];
        R[rr] = acc[rr];
    }
#pragma unroll
    for (int j = 1; j <= RAD; ++j) {
#pragma unroll
        for (int i = 7; i > 0; --i) L[i] = L[i - 1];
        L[0] = HLD(RAD - j);
#pragma unroll
        for (int i = 0; i < 7; ++i) R[i] = R[i + 1];
        R[7] = HLD(RAD + 7 + j);
        const float pj = (float)(j * j);
#pragma unroll
        for (int rr = 0; rr < 8; ++rr)
            acc[rr] = fmaxf(acc[rr], fmaf(pc, pj, fmaxf(L[rr], R[rr])));
    }
#undef HLD

    float* dp = g_t1 + (((size_t)bc * Sn + K) * Hd + h) * Wd + lane * 8;
    reinterpret_cast<float4*>(dp)[0] = make_float4(acc[0], acc[1], acc[2], acc[3]);
    reinterpret_cast<float4*>(dp)[1] = make_float4(acc[4], acc[5], acc[6], acc[7]);
}

__global__ void __launch_bounds__(256) dh_all(const float* __restrict__ ext,
                                              const float* __restrict__ cptr)
{
    __shared__ float sb[8 * 41 * 8];
    switch (blockIdx.y) {                     // heavy K first (dispatch order)
        case 0:  dh_impl<3>(sb, ext, cptr); break;
        case 1:  dh_impl<2>(sb, ext, cptr); break;
        case 2:  dh_impl<1>(sb, ext, cptr); break;
        default: dh_impl<0>(sb, ext, cptr); break;
    }
}

// ---------------------------------------------------------------------------
// Vertical streaming helper (16 rows/thread-col); loads batched 4 j-steps
// ahead (8 back-to-back LDG, MLP=8) to cover L2 latency. RAD % 4 == 0.
// ---------------------------------------------------------------------------
template <int RAD, bool ISMAX, bool SAFE>
__device__ __forceinline__ void vstream(const float* __restrict__ sp,
                                        const int r0, const float pc,
                                        float acc[16])
{
    constexpr float PADV = ISMAX ? -10000.0f : 10000.0f;
#define VLD(ROW)                                                               \
    (SAFE ? sp[(size_t)(ROW) * Wd]                                             \
          : (((unsigned)(ROW) < (unsigned)Hd) ? sp[(size_t)(ROW) * Wd] : PADV))

    float T[16], B[16];
#pragma unroll
    for (int rr = 0; rr < 16; ++rr) {
        acc[rr] = VLD(r0 + rr);
        T[rr] = acc[rr];
        B[rr] = acc[rr];
    }
#pragma unroll
    for (int jb = 1; jb <= RAD; jb += 4) {
        float nt[4], nb[4];
#pragma unroll
        for (int u = 0; u < 4; ++u) {
            nt[u] = VLD(r0 - (jb + u));
            nb[u] = VLD(r0 + 15 + (jb + u));
        }
#pragma unroll
        for (int u = 0; u < 4; ++u) {
#pragma unroll
            for (int i = 15; i > 0; --i) T[i] = T[i - 1];
            T[0] = nt[u];
#pragma unroll
            for (int i = 0; i < 15; ++i) B[i] = B[i + 1];
            B[15] = nb[u];
            const int j = jb + u;
            const float pj = (float)(j * j);
#pragma unroll
            for (int rr = 0; rr < 16; ++rr) {
                const float m = ISMAX ? fmaxf(T[rr], B[rr]) : fminf(T[rr], B[rr]);
                const float t = fmaf(pc, pj, m);
                acc[rr] = ISMAX ? fmaxf(acc[rr], t) : fminf(acc[rr], t);
            }
        }
    }
#undef VLD
}

// ---------------------------------------------------------------------------
// Fused Dv + Eh: t1 -> vertical dilation -> transposed padded smem tile ->
// horizontal erosion (warp = 2 rows, 8 outputs each) -> t2.
// ---------------------------------------------------------------------------
template <int K>
__device__ __forceinline__ void dveh_impl(float* sb, const float* __restrict__ cptr)
{
    constexpr int   RAD   = 4 << K;
    constexpr int   SPW   = Wd + 2 * RAD;
    constexpr int   PITCH = SPW / 8 + 1;      // 34/37/41/49
    constexpr float INV4T = 1.0f / (float)(1 << (2 * K + 2));
    const float cc  = __ldg(cptr);
    const float pcD = -cc * INV4T;
    const float pcE =  cc * INV4T;

    const int x  = threadIdx.x;
    const int r0 = blockIdx.x * 16;
    const int bc = blockIdx.y;

    // ---- vertical dilation ----
    const float* sp = g_t1 + ((size_t)(bc * Sn + K) * Hd) * Wd + x;
    float acc[16];
    if (r0 >= RAD && r0 + 15 + RAD < Hd)
        vstream<RAD, true, true >(sp, r0, pcD, acc);
    else
        vstream<RAD, true, false>(sp, r0, pcD, acc);

    // ---- stash transposed, pad cols with +10000 ----
    {
        const int X = x + RAD;
        const int ca = (X & 7) * PITCH + (X >> 3);
#pragma unroll
        for (int rr = 0; rr < 16; ++rr) sb[rr * 8 * PITCH + ca] = acc[rr];
        for (int i = threadIdx.x; i < 2 * RAD * 16; i += 256) {
            const int col = i & (2 * RAD - 1), r = i / (2 * RAD);
            const int Xp = (col < RAD) ? col : (col + Wd);
            sb[(r * 8 + (Xp & 7)) * PITCH + (Xp >> 3)] = 10000.0f;
        }
    }
    __syncthreads();

    // ---- horizontal erosion: warp w -> rows 2w, 2w+1 ----
    const int w = threadIdx.x >> 5, q = threadIdx.x & 31;
    const float* rbA = sb + (2 * w) * 8 * PITCH + q;
    const float* rbB = rbA + 8 * PITCH;
#define CA(C) ((((C) & 7) * PITCH) + ((C) >> 3))

    float eA[8], eB[8], LA[8], RA_[8], LB[8], RB[8];
#pragma unroll
    for (int rr = 0; rr < 8; ++rr) {
        eA[rr] = rbA[CA(RAD + rr)];  LA[rr] = eA[rr];  RA_[rr] = eA[rr];
        eB[rr] = rbB[CA(RAD + rr)];  LB[rr] = eB[rr];  RB[rr] = eB[rr];
    }
#pragma unroll
    for (int j = 1; j <= RAD; ++j) {
#pragma unroll
        for (int i = 7; i > 0; --i) { LA[i] = LA[i - 1]; LB[i] = LB[i - 1]; }
        LA[0] = rbA[CA(RAD - j)];
        LB[0] = rbB[CA(RAD - j)];
#pragma unroll
        for (int i = 0; i < 7; ++i) { RA_[i] = RA_[i + 1]; RB[i] = RB[i + 1]; }
        RA_[7] = rbA[CA(RAD + 7 + j)];
        RB[7] = rbB[CA(RAD + 7 + j)];
        const float pj = (float)(j * j);
#pragma unroll
        for (int rr = 0; rr < 8; ++rr) {
            eA[rr] = fminf(eA[rr], fmaf(pcE, pj, fminf(LA[rr], RA_[rr])));
            eB[rr] = fminf(eB[rr], fmaf(pcE, pj, fminf(LB[rr], RB[rr])));
        }
    }
#undef CA

    float* dp = g_t2 + (((size_t)bc * Sn + K) * Hd + r0 + 2 * w) * Wd + q * 8;
    reinterpret_cast<float4*>(dp)[0] = make_float4(eA[0], eA[1], eA[2], eA[3]);
    reinterpret_cast<float4*>(dp)[1] = make_float4(eA[4], eA[5], eA[6], eA[7]);
    reinterpret_cast<float4*>(dp + Wd)[0] = make_float4(eB[0], eB[1], eB[2], eB[3]);
    reinterpret_cast<float4*>(dp + Wd)[1] = make_float4(eB[4], eB[5], eB[6], eB[7]);
}

__global__ void __launch_bounds__(256, 4) dveh_all(const float* __restrict__ cptr)
{
    __shared__ float sb[16 * 8 * 49];         // K=3 worst case (24.5 KB)
    switch (blockIdx.z) {                     // heavy K first
        case 0:  dveh_impl<3>(sb, cptr); break;
        case 1:  dveh_impl<2>(sb, cptr); break;
        case 2:  dveh_impl<1>(sb, cptr); break;
        default: dveh_impl<0>(sb, cptr); break;
    }
}

// ---------------------------------------------------------------------------
// Ev: vertical erosion, t2 -> out. 16 rows/thread-col, batched loads.
// ---------------------------------------------------------------------------
template <int K>
__device__ __forceinline__ void ev_impl(float* __restrict__ out,
                                        const float* __restrict__ cptr)
{
    constexpr int   RAD   = 4 << K;
    constexpr float INV4T = 1.0f / (float)(1 << (2 * K + 2));
    const float pc = __ldg(cptr) * INV4T;

    const int x  = threadIdx.x;
    const int r0 = blockIdx.x * 16;
    const int bc = blockIdx.y;

    const float* sp = g_t2 + ((size_t)(bc * Sn + K) * Hd) * Wd + x;
    float acc[16];
    if (r0 >= RAD && r0 + 15 + RAD < Hd)
        vstream<RAD, false, true >(sp, r0, pc, acc);
    else
        vstream<RAD, false, false>(sp, r0, pc, acc);

    float* dp = out + (((size_t)bc * Sn + K) * Hd + r0) * Wd + x;
#pragma unroll
    for (int rr = 0; rr < 16; ++rr) dp[(size_t)rr * Wd] = acc[rr];
}

__global__ void __launch_bounds__(256, 4) ev_all(float* __restrict__ out,
                                                 const float* __restrict__ cptr)
{
    switch (blockIdx.z) {                     // heavy K first
        case 0:  ev_impl<3>(out, cptr); break;
        case 1:  ev_impl<2>(out, cptr); break;
        case 2:  ev_impl<1>(out, cptr); break;
        default: ev_impl<0>(out, cptr); break;
    }
}

// ---------------------------------------------------------------------------
// 3 launches: Dh ; Dv+Eh fused ; Ev.  Graph-capturable, no allocations.
// ---------------------------------------------------------------------------
extern "C" void kernel_launch(void* const* d_in, const int* in_sizes, int n_in,
                              void* d_out, int out_size)
{
    const float* in = (const float*)d_in[0];
    const float* cp = (const float*)d_in[1];
    float* out = (float*)d_out;

    dh_all  <<<dim3(BCn * Hd / 8, Sn), 256>>>(in, cp);   // in -> t1
    dveh_all<<<dim3(Hd / 16, BCn, Sn), 256>>>(cp);       // t1 -> t2
    ev_all  <<<dim3(Hd / 16, BCn, Sn), 256>>>(out, cp);  // t2 -> out
}